// round 1
// baseline (speedup 1.0000x reference)
#include <cuda_runtime.h>

#define D 1024
#define H 8
#define MAX_T 16384
#define NEG_INF (-3.402823466e38f)

// Scratch for the input projection e[t][j] = (x @ W_ih^T)[t][j] + b_ih[j] + b_hh[j]
__device__ float g_e[MAX_T * H];

// ---------------------------------------------------------------------------
// Kernel 1: skinny GEMM  e[T,8] = x[T,1024] @ W_ih^T + (b_ih + b_hh)
// One warp per row t. W_ih staged in shared (32KB), x read coalesced float4.
// HBM-bound: reads 64MB of x exactly once.
// ---------------------------------------------------------------------------
__global__ __launch_bounds__(256)
void rnn_input_proj(const float* __restrict__ x,
                    const float* __restrict__ W_ih,
                    const float* __restrict__ b_ih,
                    const float* __restrict__ b_hh,
                    int T) {
    __shared__ float4 sW[H * (D / 4)];   // 8 * 256 float4 = 32KB
    __shared__ float  sb[H];

    int tid = threadIdx.x;
    for (int i = tid; i < H * (D / 4); i += blockDim.x)
        sW[i] = ((const float4*)W_ih)[i];
    if (tid < H) sb[tid] = b_ih[tid] + b_hh[tid];
    __syncthreads();

    int warp = tid >> 5, lane = tid & 31;
    int row = blockIdx.x * (blockDim.x >> 5) + warp;
    if (row >= T) return;

    const float4* xr = (const float4*)(x + (size_t)row * D);
    float acc[H];
#pragma unroll
    for (int j = 0; j < H; j++) acc[j] = 0.f;

#pragma unroll
    for (int i = 0; i < (D / 4) / 32; i++) {        // 8 iterations
        float4 xv = xr[lane + i * 32];
#pragma unroll
        for (int j = 0; j < H; j++) {
            float4 wv = sW[j * (D / 4) + lane + i * 32];
            acc[j] += xv.x * wv.x + xv.y * wv.y + xv.z * wv.z + xv.w * wv.w;
        }
    }

#pragma unroll
    for (int j = 0; j < H; j++) {
#pragma unroll
        for (int o = 16; o > 0; o >>= 1)
            acc[j] += __shfl_xor_sync(0xffffffffu, acc[j], o);
    }

    if (lane == 0) {
        float4 v0 = make_float4(acc[0] + sb[0], acc[1] + sb[1],
                                acc[2] + sb[2], acc[3] + sb[3]);
        float4 v1 = make_float4(acc[4] + sb[4], acc[5] + sb[5],
                                acc[6] + sb[6], acc[7] + sb[7]);
        float4* ep = (float4*)(g_e + (size_t)row * H);
        ep[0] = v0;
        ep[1] = v1;
    }
}

// ---------------------------------------------------------------------------
// Kernel 2: parallel scan of the relu recurrence + fused output projection.
//
// With diagonal, non-negative W_hh (diag d), each channel j independently obeys
//   h_t = max(d*h_{t-1} + e_t, 0)
// The affine-max maps  h -> max(c*h + a, b)  (c >= 0) are closed under
// composition:
//   (c1,a1,b1) then (c2,a2,b2)  =  (c1*c2, c2*a1 + a2, max(c2*b1 + a2, b2))
// identity = (1, 0, -inf). Associative => hierarchical scan:
//   per-thread serial aggregate over a chunk of 16 steps
//   -> warp inclusive scan (shfl)
//   -> cross-warp scan (warp 0)
//   -> each thread replays its chunk from the exclusive prefix and emits
//      out_t = h_t . W_out + b_out.
// A serial fallback (thread 0) covers non-diagonal / negative-diag W_hh.
// ---------------------------------------------------------------------------
__global__ __launch_bounds__(1024, 1)
void rnn_scan_out(const float* __restrict__ W_hh,
                  const float* __restrict__ W_out,
                  const float* __restrict__ b_out,
                  float* __restrict__ out, int T) {
    __shared__ float sd[H], swout[H], sWhh[H * H];
    __shared__ float sbout;
    __shared__ int   s_fb;
    __shared__ float wc[32][H], wa[32][H], wb[32][H];

    int tid = threadIdx.x;
    if (tid == 0) {
        int bad = 0;
        for (int i = 0; i < H; i++)
            for (int j = 0; j < H; j++) {
                float v = W_hh[i * H + j];
                sWhh[i * H + j] = v;
                if (i != j && v != 0.f) bad = 1;
            }
        for (int i = 0; i < H; i++) {
            float dv = sWhh[i * H + i];
            sd[i] = dv;
            if (!(dv >= 0.f)) bad = 1;   // need c >= 0 for max distribution
            swout[i] = W_out[i];
        }
        sbout = b_out[0];
        s_fb  = bad;
    }
    __syncthreads();

    if (s_fb) {
        // Correctness fallback: fully serial recurrence (never taken for the
        // dataset's identity W_hh; exists so the fast path is an optimization,
        // not an assumption).
        if (tid == 0) {
            float h[H];
            for (int j = 0; j < H; j++) h[j] = 0.f;
            for (int t = 0; t < T; t++) {
                float hn[H];
                for (int j = 0; j < H; j++) {
                    float s = g_e[(size_t)t * H + j];
                    for (int k = 0; k < H; k++) s += sWhh[j * H + k] * h[k];
                    hn[j] = fmaxf(s, 0.f);
                }
                float o = sbout;
                for (int j = 0; j < H; j++) { h[j] = hn[j]; o += h[j] * swout[j]; }
                out[t] = o;
            }
        }
        return;
    }

    const int nth   = blockDim.x;      // 1024
    const int chunk = T / nth;         // 16 for T=16384
    const int t0    = tid * chunk;
    const int lane  = tid & 31;
    const int wid   = tid >> 5;

    float d[H], c[H], a[H], b[H];
#pragma unroll
    for (int j = 0; j < H; j++) {
        d[j] = sd[j]; c[j] = 1.f; a[j] = 0.f; b[j] = NEG_INF;
    }

    // ---- pass 1: serial aggregate over this thread's chunk ----
    for (int k = 0; k < chunk; k++) {
        const float4* ep = (const float4*)(g_e + (size_t)(t0 + k) * H);
        float4 e0 = ep[0], e1 = ep[1];
        float ev[H] = {e0.x, e0.y, e0.z, e0.w, e1.x, e1.y, e1.z, e1.w};
#pragma unroll
        for (int j = 0; j < H; j++) {
            // compose current aggregate with step map (d, e, 0)
            c[j] = c[j] * d[j];
            a[j] = d[j] * a[j] + ev[j];
            b[j] = fmaxf(d[j] * b[j] + ev[j], 0.f);
        }
    }

    // ---- warp inclusive scan (Hillis-Steele, shfl_up) ----
#pragma unroll
    for (int off = 1; off < 32; off <<= 1) {
#pragma unroll
        for (int j = 0; j < H; j++) {
            float lc = __shfl_up_sync(0xffffffffu, c[j], off);
            float la = __shfl_up_sync(0xffffffffu, a[j], off);
            float lb = __shfl_up_sync(0xffffffffu, b[j], off);
            if (lane >= off) {
                // combine(left, mine): b' first (uses old a), then a', then c'
                b[j] = fmaxf(c[j] * lb + a[j], b[j]);
                a[j] = c[j] * la + a[j];
                c[j] = c[j] * lc;
            }
        }
    }

    if (lane == 31) {
#pragma unroll
        for (int j = 0; j < H; j++) {
            wc[wid][j] = c[j]; wa[wid][j] = a[j]; wb[wid][j] = b[j];
        }
    }
    __syncthreads();

    // ---- warp 0 scans the 32 warp aggregates ----
    if (wid == 0) {
        float cc[H], aa[H], bb[H];
#pragma unroll
        for (int j = 0; j < H; j++) {
            cc[j] = wc[lane][j]; aa[j] = wa[lane][j]; bb[j] = wb[lane][j];
        }
#pragma unroll
        for (int off = 1; off < 32; off <<= 1) {
#pragma unroll
            for (int j = 0; j < H; j++) {
                float lc = __shfl_up_sync(0xffffffffu, cc[j], off);
                float la = __shfl_up_sync(0xffffffffu, aa[j], off);
                float lb = __shfl_up_sync(0xffffffffu, bb[j], off);
                if (lane >= off) {
                    bb[j] = fmaxf(cc[j] * lb + aa[j], bb[j]);
                    aa[j] = cc[j] * la + aa[j];
                    cc[j] = cc[j] * lc;
                }
            }
        }
#pragma unroll
        for (int j = 0; j < H; j++) {
            wc[lane][j] = cc[j]; wa[lane][j] = aa[j]; wb[lane][j] = bb[j];
        }
    }
    __syncthreads();

    // ---- thread-exclusive prefix = combine(warp_prefix, lane_exclusive) ----
    float h[H];
#pragma unroll
    for (int j = 0; j < H; j++) {
        float lc = __shfl_up_sync(0xffffffffu, c[j], 1);
        float la = __shfl_up_sync(0xffffffffu, a[j], 1);
        float lb = __shfl_up_sync(0xffffffffu, b[j], 1);
        if (lane == 0) { lc = 1.f; la = 0.f; lb = NEG_INF; }

        float pc, pa, pb;
        if (wid > 0) { pc = wc[wid - 1][j]; pa = wa[wid - 1][j]; pb = wb[wid - 1][j]; }
        else         { pc = 1.f; pa = 0.f; pb = NEG_INF; }

        // excl = combine(prefix, lane_excl); apply to h0 = 0 -> max(a, b)
        float ea = lc * pa + la;
        float eb = fmaxf(lc * pb + la, lb);
        h[j] = fmaxf(ea, eb);
    }

    // ---- pass 2: replay chunk from h_in, emit fused output projection ----
    for (int k = 0; k < chunk; k++) {
        const float4* ep = (const float4*)(g_e + (size_t)(t0 + k) * H);
        float4 e0 = ep[0], e1 = ep[1];
        float ev[H] = {e0.x, e0.y, e0.z, e0.w, e1.x, e1.y, e1.z, e1.w};
        float o = sbout;
#pragma unroll
        for (int j = 0; j < H; j++) {
            h[j] = fmaxf(d[j] * h[j] + ev[j], 0.f);
            o += h[j] * swout[j];
        }
        out[t0 + k] = o;
    }
}

// ---------------------------------------------------------------------------
// kernel_launch: inputs in metadata order:
//   0: x [1,16384,1024] f32   1: W_ih [8,1024]  2: b_ih [8]
//   3: W_hh [8,8]             4: b_hh [8]       5: W_out [1,8]   6: b_out [1]
// output: [1,16384,1] f32
// ---------------------------------------------------------------------------
extern "C" void kernel_launch(void* const* d_in, const int* in_sizes, int n_in,
                              void* d_out, int out_size) {
    const float* x     = (const float*)d_in[0];
    const float* W_ih  = (const float*)d_in[1];
    const float* b_ih  = (const float*)d_in[2];
    const float* W_hh  = (const float*)d_in[3];
    const float* b_hh  = (const float*)d_in[4];
    const float* W_out = (const float*)d_in[5];
    const float* b_out = (const float*)d_in[6];
    float* out = (float*)d_out;

    int T = in_sizes[0] / D;   // 16384

    // 8 rows (warps) per 256-thread block
    rnn_input_proj<<<(T + 7) / 8, 256>>>(x, W_ih, b_ih, b_hh, T);
    rnn_scan_out<<<1, 1024>>>(W_hh, W_out, b_out, out, T);
}

// round 2
// speedup vs baseline: 1.0058x; 1.0058x over previous
#include <cuda_runtime.h>

#define D 1024
#define H 8
#define MAX_T 16384
#define NEG_INF (-3.402823466e38f)

// Scratch for the input projection e[t][j] = (x @ W_ih^T)[t][j] + b_ih[j] + b_hh[j]
__device__ float g_e[MAX_T * H];

// ---------------------------------------------------------------------------
// Kernel 1: skinny GEMM  e[T,8] = x[T,1024] @ W_ih^T + (b_ih + b_hh)
// One warp per row t. W_ih staged in shared (32KB), x read coalesced float4.
// HBM-bound: reads 64MB of x exactly once.
// ---------------------------------------------------------------------------
__global__ __launch_bounds__(256)
void rnn_input_proj(const float* __restrict__ x,
                    const float* __restrict__ W_ih,
                    const float* __restrict__ b_ih,
                    const float* __restrict__ b_hh,
                    int T) {
    __shared__ float4 sW[H * (D / 4)];   // 8 * 256 float4 = 32KB
    __shared__ float  sb[H];

    int tid = threadIdx.x;
    for (int i = tid; i < H * (D / 4); i += blockDim.x)
        sW[i] = ((const float4*)W_ih)[i];
    if (tid < H) sb[tid] = b_ih[tid] + b_hh[tid];
    __syncthreads();

    int warp = tid >> 5, lane = tid & 31;
    int row = blockIdx.x * (blockDim.x >> 5) + warp;
    if (row >= T) return;

    const float4* xr = (const float4*)(x + (size_t)row * D);
    float acc[H];
#pragma unroll
    for (int j = 0; j < H; j++) acc[j] = 0.f;

#pragma unroll
    for (int i = 0; i < (D / 4) / 32; i++) {        // 8 iterations
        float4 xv = xr[lane + i * 32];
#pragma unroll
        for (int j = 0; j < H; j++) {
            float4 wv = sW[j * (D / 4) + lane + i * 32];
            acc[j] += xv.x * wv.x + xv.y * wv.y + xv.z * wv.z + xv.w * wv.w;
        }
    }

#pragma unroll
    for (int j = 0; j < H; j++) {
#pragma unroll
        for (int o = 16; o > 0; o >>= 1)
            acc[j] += __shfl_xor_sync(0xffffffffu, acc[j], o);
    }

    if (lane == 0) {
        float4 v0 = make_float4(acc[0] + sb[0], acc[1] + sb[1],
                                acc[2] + sb[2], acc[3] + sb[3]);
        float4 v1 = make_float4(acc[4] + sb[4], acc[5] + sb[5],
                                acc[6] + sb[6], acc[7] + sb[7]);
        float4* ep = (float4*)(g_e + (size_t)row * H);
        ep[0] = v0;
        ep[1] = v1;
    }
}

// ---------------------------------------------------------------------------
// Kernel 2: parallel scan of the relu recurrence + fused output projection.
//
// With diagonal, non-negative W_hh (diag d), each channel j independently obeys
//   h_t = max(d*h_{t-1} + e_t, 0)
// The affine-max maps  h -> max(c*h + a, b)  (c >= 0) are closed under
// composition:
//   (c1,a1,b1) then (c2,a2,b2)  =  (c1*c2, c2*a1 + a2, max(c2*b1 + a2, b2))
// identity = (1, 0, -inf). Associative => hierarchical scan:
//   per-thread serial aggregate over a chunk of 16 steps
//   -> warp inclusive scan (shfl)
//   -> cross-warp scan (warp 0)
//   -> each thread replays its chunk from the exclusive prefix and emits
//      out_t = h_t . W_out + b_out.
// A serial fallback (thread 0) covers non-diagonal / negative-diag W_hh.
// ---------------------------------------------------------------------------
__global__ __launch_bounds__(1024, 1)
void rnn_scan_out(const float* __restrict__ W_hh,
                  const float* __restrict__ W_out,
                  const float* __restrict__ b_out,
                  float* __restrict__ out, int T) {
    __shared__ float sd[H], swout[H], sWhh[H * H];
    __shared__ float sbout;
    __shared__ int   s_fb;
    __shared__ float wc[32][H], wa[32][H], wb[32][H];

    int tid = threadIdx.x;
    if (tid == 0) {
        int bad = 0;
        for (int i = 0; i < H; i++)
            for (int j = 0; j < H; j++) {
                float v = W_hh[i * H + j];
                sWhh[i * H + j] = v;
                if (i != j && v != 0.f) bad = 1;
            }
        for (int i = 0; i < H; i++) {
            float dv = sWhh[i * H + i];
            sd[i] = dv;
            if (!(dv >= 0.f)) bad = 1;   // need c >= 0 for max distribution
            swout[i] = W_out[i];
        }
        sbout = b_out[0];
        s_fb  = bad;
    }
    __syncthreads();

    if (s_fb) {
        // Correctness fallback: fully serial recurrence (never taken for the
        // dataset's identity W_hh; exists so the fast path is an optimization,
        // not an assumption).
        if (tid == 0) {
            float h[H];
            for (int j = 0; j < H; j++) h[j] = 0.f;
            for (int t = 0; t < T; t++) {
                float hn[H];
                for (int j = 0; j < H; j++) {
                    float s = g_e[(size_t)t * H + j];
                    for (int k = 0; k < H; k++) s += sWhh[j * H + k] * h[k];
                    hn[j] = fmaxf(s, 0.f);
                }
                float o = sbout;
                for (int j = 0; j < H; j++) { h[j] = hn[j]; o += h[j] * swout[j]; }
                out[t] = o;
            }
        }
        return;
    }

    const int nth   = blockDim.x;      // 1024
    const int chunk = T / nth;         // 16 for T=16384
    const int t0    = tid * chunk;
    const int lane  = tid & 31;
    const int wid   = tid >> 5;

    float d[H], c[H], a[H], b[H];
#pragma unroll
    for (int j = 0; j < H; j++) {
        d[j] = sd[j]; c[j] = 1.f; a[j] = 0.f; b[j] = NEG_INF;
    }

    // ---- pass 1: serial aggregate over this thread's chunk ----
    for (int k = 0; k < chunk; k++) {
        const float4* ep = (const float4*)(g_e + (size_t)(t0 + k) * H);
        float4 e0 = ep[0], e1 = ep[1];
        float ev[H] = {e0.x, e0.y, e0.z, e0.w, e1.x, e1.y, e1.z, e1.w};
#pragma unroll
        for (int j = 0; j < H; j++) {
            // compose current aggregate with step map (d, e, 0)
            c[j] = c[j] * d[j];
            a[j] = d[j] * a[j] + ev[j];
            b[j] = fmaxf(d[j] * b[j] + ev[j], 0.f);
        }
    }

    // ---- warp inclusive scan (Hillis-Steele, shfl_up) ----
#pragma unroll
    for (int off = 1; off < 32; off <<= 1) {
#pragma unroll
        for (int j = 0; j < H; j++) {
            float lc = __shfl_up_sync(0xffffffffu, c[j], off);
            float la = __shfl_up_sync(0xffffffffu, a[j], off);
            float lb = __shfl_up_sync(0xffffffffu, b[j], off);
            if (lane >= off) {
                // combine(left, mine): b' first (uses old a), then a', then c'
                b[j] = fmaxf(c[j] * lb + a[j], b[j]);
                a[j] = c[j] * la + a[j];
                c[j] = c[j] * lc;
            }
        }
    }

    if (lane == 31) {
#pragma unroll
        for (int j = 0; j < H; j++) {
            wc[wid][j] = c[j]; wa[wid][j] = a[j]; wb[wid][j] = b[j];
        }
    }
    __syncthreads();

    // ---- warp 0 scans the 32 warp aggregates ----
    if (wid == 0) {
        float cc[H], aa[H], bb[H];
#pragma unroll
        for (int j = 0; j < H; j++) {
            cc[j] = wc[lane][j]; aa[j] = wa[lane][j]; bb[j] = wb[lane][j];
        }
#pragma unroll
        for (int off = 1; off < 32; off <<= 1) {
#pragma unroll
            for (int j = 0; j < H; j++) {
                float lc = __shfl_up_sync(0xffffffffu, cc[j], off);
                float la = __shfl_up_sync(0xffffffffu, aa[j], off);
                float lb = __shfl_up_sync(0xffffffffu, bb[j], off);
                if (lane >= off) {
                    bb[j] = fmaxf(cc[j] * lb + aa[j], bb[j]);
                    aa[j] = cc[j] * la + aa[j];
                    cc[j] = cc[j] * lc;
                }
            }
        }
#pragma unroll
        for (int j = 0; j < H; j++) {
            wc[lane][j] = cc[j]; wa[lane][j] = aa[j]; wb[lane][j] = bb[j];
        }
    }
    __syncthreads();

    // ---- thread-exclusive prefix = combine(warp_prefix, lane_exclusive) ----
    float h[H];
#pragma unroll
    for (int j = 0; j < H; j++) {
        float lc = __shfl_up_sync(0xffffffffu, c[j], 1);
        float la = __shfl_up_sync(0xffffffffu, a[j], 1);
        float lb = __shfl_up_sync(0xffffffffu, b[j], 1);
        if (lane == 0) { lc = 1.f; la = 0.f; lb = NEG_INF; }

        float pc, pa, pb;
        if (wid > 0) { pc = wc[wid - 1][j]; pa = wa[wid - 1][j]; pb = wb[wid - 1][j]; }
        else         { pc = 1.f; pa = 0.f; pb = NEG_INF; }

        // excl = combine(prefix, lane_excl); apply to h0 = 0 -> max(a, b)
        float ea = lc * pa + la;
        float eb = fmaxf(lc * pb + la, lb);
        h[j] = fmaxf(ea, eb);
    }

    // ---- pass 2: replay chunk from h_in, emit fused output projection ----
    for (int k = 0; k < chunk; k++) {
        const float4* ep = (const float4*)(g_e + (size_t)(t0 + k) * H);
        float4 e0 = ep[0], e1 = ep[1];
        float ev[H] = {e0.x, e0.y, e0.z, e0.w, e1.x, e1.y, e1.z, e1.w};
        float o = sbout;
#pragma unroll
        for (int j = 0; j < H; j++) {
            h[j] = fmaxf(d[j] * h[j] + ev[j], 0.f);
            o += h[j] * swout[j];
        }
        out[t0 + k] = o;
    }
}

// ---------------------------------------------------------------------------
// kernel_launch: inputs in metadata order:
//   0: x [1,16384,1024] f32   1: W_ih [8,1024]  2: b_ih [8]
//   3: W_hh [8,8]             4: b_hh [8]       5: W_out [1,8]   6: b_out [1]
// output: [1,16384,1] f32
// ---------------------------------------------------------------------------
extern "C" void kernel_launch(void* const* d_in, const int* in_sizes, int n_in,
                              void* d_out, int out_size) {
    const float* x     = (const float*)d_in[0];
    const float* W_ih  = (const float*)d_in[1];
    const float* b_ih  = (const float*)d_in[2];
    const float* W_hh  = (const float*)d_in[3];
    const float* b_hh  = (const float*)d_in[4];
    const float* W_out = (const float*)d_in[5];
    const float* b_out = (const float*)d_in[6];
    float* out = (float*)d_out;

    int T = in_sizes[0] / D;   // 16384

    // 8 rows (warps) per 256-thread block
    rnn_input_proj<<<(T + 7) / 8, 256>>>(x, W_ih, b_ih, b_hh, T);
    rnn_scan_out<<<1, 1024>>>(W_hh, W_out, b_out, out, T);
}